// round 4
// baseline (speedup 1.0000x reference)
#include <cuda_runtime.h>
#include <cstdint>
#include <cstddef>

// Problem constants
#define NB   4096
#define NN   29
#define NC   6
#define CDIM 16
#define DD   22
#define HDIM 64
#define NL   2
#define NOUT 24
#define OUTROW 12
#define ZROW 25
#define PROW 76
#define CATW 100

// Shared memory layout (float offsets)
#define OFF_Z    0        // 800
#define OFF_ZN   800      // 800
#define OFF_PI   1600     // 32*76 = 2432
#define OFF_PJ   4032     // 2432
#define OFF_EW1  6464     // 44*64 = 2816
#define OFF_MAGG 9280     // 32*64 = 2048
#define OFF_H    11328    // 2048
#define OFF_GPB  13376    // 2*2*4*32 = 512 (gate exchange, dbl-buffered)
#define OFF_EBG  13888    // 128 (eb2 | gW)
#define SMEM_FLOATS 14016 // 56064 bytes
// catsh [32][100]=3200 aliases OFF_PI (piR+pjR dead after tile loop)

__device__ __forceinline__ float tanhfast(float x) {
    float y;
    asm("tanh.approx.f32 %0, %1;" : "=f"(y) : "f"(x));
    return y;
}
__device__ __forceinline__ float silu_t(float v) {
    float h = 0.5f * v;
    return fmaf(h, tanhfast(h), h);
}
__device__ __forceinline__ float sigm_t(float v) {
    return fmaf(0.5f, tanhfast(0.5f * v), 0.5f);
}
__device__ __forceinline__ uint32_t tf32_rna(float x) {
    uint32_t u;
    asm("cvt.rna.tf32.f32 %0, %1;" : "=r"(u) : "f"(x));
    return u;
}
__device__ __forceinline__ void mma_tf32(float c[4], uint32_t a0, uint32_t a1,
                                         uint32_t a2, uint32_t a3,
                                         uint32_t b0, uint32_t b1) {
    asm volatile(
        "mma.sync.aligned.m16n8k8.row.col.f32.tf32.tf32.f32 "
        "{%0,%1,%2,%3}, {%4,%5,%6,%7}, {%8,%9}, {%0,%1,%2,%3};\n"
        : "+f"(c[0]), "+f"(c[1]), "+f"(c[2]), "+f"(c[3])
        : "r"(a0), "r"(a1), "r"(a2), "r"(a3), "r"(b0), "r"(b1));
}

extern "C" __global__ void __launch_bounds__(256, 2)
gnn_kernel(const float* __restrict__ x,   const float* __restrict__ ctx,
           const float* __restrict__ eW1, const float* __restrict__ eb1,
           const float* __restrict__ eW2, const float* __restrict__ eb2,
           const float* __restrict__ gW,  const float* __restrict__ gb,
           const float* __restrict__ lng, const float* __restrict__ lnb,
           const float* __restrict__ nW1, const float* __restrict__ nb1,
           const float* __restrict__ nW2, const float* __restrict__ nb2,
           const float* __restrict__ hW1, const float* __restrict__ hb1,
           const float* __restrict__ hW2, const float* __restrict__ hb2,
           float* __restrict__ out)
{
    extern __shared__ float sh[];
    float* zsh   = sh + OFF_Z;
    float* znsh  = sh + OFF_ZN;
    float* piR   = sh + OFF_PI;    // [32][76]
    float* pjR   = sh + OFF_PJ;    // [32][76]
    float* ew1sh = sh + OFF_EW1;   // [44][64]
    float* magg  = sh + OFF_MAGG;  // [32][64]
    float* hbuf  = sh + OFF_H;     // [32][64]
    float* gpb   = sh + OFF_GPB;   // [par][ch][i_sel][32]
    float* ebg   = sh + OFF_EBG;   // [eb2(64) | gW(64)]
    float* catsh = sh + OFF_PI;    // [32][100] (aliases piR/pjR)

    const int b = blockIdx.x;
    const int t = threadIdx.x;
    const int w = t >> 5;
    const int lane = t & 31;
    const int lq = lane >> 2;
    const int cq = lane & 3;
    const int i_sel = w & 3;       // node within i-group
    const int ch = w >> 2;         // column half 0/1

    // ---- load z = concat(x, context) ----
    for (int idx = t; idx < NN * DD; idx += 256) {
        int i = idx / DD, d = idx - i * DD;
        float v = (d < NC) ? x[(b * NN + i) * NC + d]
                           : ctx[(b * NN + i) * CDIM + (d - NC)];
        zsh[i * ZROW + d] = v;
    }
    __syncthreads();

    for (int l = 0; l < NL; ++l) {
        const float* eW1l = eW1 + l * 2 * DD * HDIM;
        const float* eb1l = eb1 + l * HDIM;
        const float* eW2l = eW2 + l * HDIM * HDIM;
        const float* eb2l = eb2 + l * HDIM;
        const float* gWl  = gW  + l * HDIM;
        const float  gbl  = gb[l];
        const float* lngl = lng + l * DD;
        const float* lnbl = lnb + l * DD;
        const float* nW1l = nW1 + l * (DD + HDIM) * HDIM;
        const float* nb1l = nb1 + l * HDIM;
        const float* nW2l = nW2 + l * HDIM * DD;
        const float* nb2l = nb2 + l * DD;

        // ---- B fragments in registers, once per layer (L2-hot) ----
        uint32_t breg[8][4][2];
        #pragma unroll
        for (int kk = 0; kk < 8; ++kk)
            #pragma unroll
            for (int nf = 0; nf < 4; ++nf) {
                int col = ch * 32 + nf * 8 + lq;
                breg[kk][nf][0] = tf32_rna(__ldg(eW2l + (kk * 8 + cq) * HDIM + col));
                breg[kk][nf][1] = tf32_rna(__ldg(eW2l + (kk * 8 + cq + 4) * HDIM + col));
            }

        // ---- stage eW1 + epilogue constants ----
        for (int idx = t; idx < 2 * DD * HDIM; idx += 256) ew1sh[idx] = eW1l[idx];
        if (t < HDIM) { ebg[t] = eb2l[t]; ebg[HDIM + t] = gWl[t]; }
        __syncthreads();

        // ---- pi / pj projections ----
        for (int idx = t; idx < 32 * HDIM; idx += 256) {
            int i = idx >> 6, k = idx & 63;
            float aI = 0.f, aJ = 0.f;
            if (i < NN) {
                #pragma unroll
                for (int d = 0; d < DD; ++d) {
                    float zv = zsh[i * ZROW + d];
                    aI += zv * ew1sh[d * HDIM + k];
                    aJ += zv * ew1sh[(DD + d) * HDIM + k];
                }
                aI += eb1l[k];
            }
            piR[i * PROW + k] = aI;
            pjR[i * PROW + k] = aJ;
        }
        // ---- layernorm ----
        if (t < NN) {
            float mu = 0.f, sq = 0.f;
            #pragma unroll
            for (int d = 0; d < DD; ++d) {
                float v = zsh[t * ZROW + d];
                mu += v; sq += v * v;
            }
            mu *= (1.0f / DD);
            float var = sq * (1.0f / DD) - mu * mu;
            float rs = rsqrtf(var + 1e-5f);
            #pragma unroll
            for (int d = 0; d < DD; ++d)
                znsh[t * ZROW + d] = (zsh[t * ZROW + d] - mu) * rs * lngl[d] + lnbl[d];
        }
        __syncthreads();

        // pj row pointers: thread's 4 rows are m*8+lq, m=0..3
        const float* pjm0 = pjR + (0 * 8 + lq) * PROW;
        const float* pjm1 = pjR + (1 * 8 + lq) * PROW;
        const float* pjm2 = pjR + (2 * 8 + lq) * PROW;
        const float* pjm3 = pjR + (3 * 8 + lq) * PROW;

        // ---- 8 tiles: warp = (node, colhalf), 32 jj x 32 cols, K=64 ----
        for (int ig = 0; ig < 8; ++ig) {
            const int node = ig * 4 + i_sel;
            const float* pib = piR + node * PROW;

            float acc[2][4][4];
            #pragma unroll
            for (int f = 0; f < 2; ++f)
                #pragma unroll
                for (int nf = 0; nf < 4; ++nf)
                    #pragma unroll
                    for (int e = 0; e < 4; ++e) acc[f][nf][e] = 0.f;

            #pragma unroll
            for (int kk = 0; kk < 8; ++kk) {
                const int k0 = kk * 8 + cq, k1 = k0 + 4;
                const float p0 = pib[k0], p1 = pib[k1];
                // frag 0: rows lq, lq+8 ; frag 1: rows lq+16, lq+24
                uint32_t a00 = tf32_rna(silu_t(p0 + pjm0[k0]));
                uint32_t a01 = tf32_rna(silu_t(p0 + pjm1[k0]));
                uint32_t a02 = tf32_rna(silu_t(p1 + pjm0[k1]));
                uint32_t a03 = tf32_rna(silu_t(p1 + pjm1[k1]));
                uint32_t a10 = tf32_rna(silu_t(p0 + pjm2[k0]));
                uint32_t a11 = tf32_rna(silu_t(p0 + pjm3[k0]));
                uint32_t a12 = tf32_rna(silu_t(p1 + pjm2[k1]));
                uint32_t a13 = tf32_rna(silu_t(p1 + pjm3[k1]));
                #pragma unroll
                for (int nf = 0; nf < 4; ++nf) {
                    mma_tf32(acc[0][nf], a00, a01, a02, a03,
                             breg[kk][nf][0], breg[kk][nf][1]);
                    mma_tf32(acc[1][nf], a10, a11, a12, a13,
                             breg[kk][nf][0], breg[kk][nf][1]);
                }
            }

            // ---- epilogue: silu+bias, gate partials over our 32 cols ----
            float gp[4] = {0.f, 0.f, 0.f, 0.f};   // rows m*8+lq
            #pragma unroll
            for (int f = 0; f < 2; ++f)
                #pragma unroll
                for (int nf = 0; nf < 4; ++nf) {
                    float2 e2 = *(const float2*)(ebg + ch * 32 + nf * 8 + 2 * cq);
                    float2 g2 = *(const float2*)(ebg + HDIM + ch * 32 + nf * 8 + 2 * cq);
                    float v0 = silu_t(acc[f][nf][0] + e2.x);
                    float v1 = silu_t(acc[f][nf][1] + e2.y);
                    float v2 = silu_t(acc[f][nf][2] + e2.x);
                    float v3 = silu_t(acc[f][nf][3] + e2.y);
                    acc[f][nf][0] = v0; acc[f][nf][1] = v1;
                    acc[f][nf][2] = v2; acc[f][nf][3] = v3;
                    gp[f * 2]     = fmaf(v0, g2.x, fmaf(v1, g2.y, gp[f * 2]));
                    gp[f * 2 + 1] = fmaf(v2, g2.x, fmaf(v3, g2.y, gp[f * 2 + 1]));
                }
            #pragma unroll
            for (int m = 0; m < 4; ++m) {
                gp[m] += __shfl_xor_sync(0xffffffffu, gp[m], 1);
                gp[m] += __shfl_xor_sync(0xffffffffu, gp[m], 2);
            }
            // exchange gate partials with colhalf twin
            float* slot = gpb + (ig & 1) * 256 + ch * 128 + i_sel * 32;
            if (cq == 0) {
                #pragma unroll
                for (int m = 0; m < 4; ++m) slot[m * 8 + lq] = gp[m];
            }
            asm volatile("bar.sync %0, %1;" :: "r"(i_sel + 1), "r"(64) : "memory");
            const float* pslot = gpb + (ig & 1) * 256 + (1 - ch) * 128 + i_sel * 32;
            float g[4];
            #pragma unroll
            for (int m = 0; m < 4; ++m) {
                int row = m * 8 + lq;
                float gt = sigm_t(gp[m] + pslot[row] + gbl);
                g[m] = (row < NN) ? gt : 0.f;
            }

            // ---- weighted j-aggregate, value-splitting reduction over lq ----
            float s8[8];
            #pragma unroll
            for (int nf = 0; nf < 4; ++nf) {
                s8[nf * 2] = fmaf(acc[0][nf][0], g[0],
                             fmaf(acc[0][nf][2], g[1],
                             fmaf(acc[1][nf][0], g[2], acc[1][nf][2] * g[3])));
                s8[nf * 2 + 1] = fmaf(acc[0][nf][1], g[0],
                                 fmaf(acc[0][nf][3], g[1],
                                 fmaf(acc[1][nf][1], g[2], acc[1][nf][3] * g[3])));
            }
            float v4[4];
            {
                int bb = lq & 1;
                #pragma unroll
                for (int j = 0; j < 4; ++j) {
                    float keep = bb ? s8[4 + j] : s8[j];
                    float send = bb ? s8[j]     : s8[4 + j];
                    v4[j] = keep + __shfl_xor_sync(0xffffffffu, send, 4);
                }
            }
            float v2a[2];
            {
                int bb = (lq >> 1) & 1;
                #pragma unroll
                for (int j = 0; j < 2; ++j) {
                    float keep = bb ? v4[2 + j] : v4[j];
                    float send = bb ? v4[j]     : v4[2 + j];
                    v2a[j] = keep + __shfl_xor_sync(0xffffffffu, send, 8);
                }
            }
            float v1f;
            {
                int bb = lq >> 2;
                float keep = bb ? v2a[1] : v2a[0];
                float send = bb ? v2a[0] : v2a[1];
                v1f = keep + __shfl_xor_sync(0xffffffffu, send, 16);
            }
            int nf_f = (lq & 1) * 2 + ((lq >> 1) & 1);
            int col = ch * 32 + nf_f * 8 + 2 * cq + (lq >> 2);
            magg[node * HDIM + col] = v1f;
        }
        __syncthreads();

        // ---- build concat buffer: [zn | m_i | 0-pad] ----
        for (int idx = t; idx < 32 * HDIM; idx += 256) {
            int i = idx >> 6, c = idx & 63;
            catsh[i * CATW + DD + c] = (i < NN) ? magg[idx] : 0.f;
        }
        for (int idx = t; idx < 32 * DD; idx += 256) {
            int i = idx / DD, d = idx - i * DD;
            catsh[i * CATW + d] = (i < NN) ? znsh[i * ZROW + d] : 0.f;
        }
        if (t < 64) catsh[(t >> 1) * CATW + 86 + (t & 1)] = 0.f;
        __syncthreads();

        // ---- node MLP layer 1 via MMA: [32 x 88] @ [86 x 64] ----
        {
            const int mh  = w & 1;
            const int nh4 = w >> 1;
            const int row0 = mh * 16 + lq, row1 = row0 + 8;
            float c2[2][4];
            #pragma unroll
            for (int nfi = 0; nfi < 2; ++nfi)
                #pragma unroll
                for (int e = 0; e < 4; ++e) c2[nfi][e] = 0.f;

            #pragma unroll
            for (int kk = 0; kk < 11; ++kk) {
                const int k0 = kk * 8 + cq, k1 = k0 + 4;
                uint32_t a0 = tf32_rna(catsh[row0 * CATW + k0]);
                uint32_t a1 = tf32_rna(catsh[row1 * CATW + k0]);
                uint32_t a2 = tf32_rna(catsh[row0 * CATW + k1]);
                uint32_t a3 = tf32_rna(catsh[row1 * CATW + k1]);
                #pragma unroll
                for (int nfi = 0; nfi < 2; ++nfi) {
                    const int col = (nh4 * 2 + nfi) * 8 + lq;
                    uint32_t b0 = tf32_rna(nW1l[k0 * HDIM + col]);
                    uint32_t b1 = (k1 < DD + HDIM)
                                ? tf32_rna(nW1l[k1 * HDIM + col]) : 0u;
                    mma_tf32(c2[nfi], a0, a1, a2, a3, b0, b1);
                }
            }
            #pragma unroll
            for (int nfi = 0; nfi < 2; ++nfi) {
                const int colb = (nh4 * 2 + nfi) * 8 + 2 * cq;
                float2 nb = *(const float2*)(nb1l + colb);
                *(float2*)(hbuf + row0 * HDIM + colb) =
                    make_float2(silu_t(c2[nfi][0] + nb.x), silu_t(c2[nfi][1] + nb.y));
                *(float2*)(hbuf + row1 * HDIM + colb) =
                    make_float2(silu_t(c2[nfi][2] + nb.x), silu_t(c2[nfi][3] + nb.y));
            }
        }
        __syncthreads();

        // ---- node MLP layer 2 + residual ----
        for (int idx = t; idx < NN * DD; idx += 256) {
            int i = idx / DD, d = idx - i * DD;
            float a = nb2l[d];
            #pragma unroll 8
            for (int m2 = 0; m2 < HDIM; ++m2)
                a += hbuf[i * HDIM + m2] * nW2l[m2 * DD + d];
            zsh[i * ZROW + d] += a;
        }
        __syncthreads();
    }

    // ---- mean pool ----
    if (t < DD) {
        float s = 0.f;
        #pragma unroll
        for (int i = 0; i < NN; ++i) s += zsh[i * ZROW + t];
        znsh[t] = s * (1.0f / NN);
    }
    __syncthreads();

    // ---- head MLP ----
    if (t < HDIM) {
        float a = hb1[t];
        #pragma unroll
        for (int d = 0; d < DD; ++d) a += znsh[d] * hW1[d * HDIM + t];
        hbuf[t] = fmaxf(a, 0.f);
    }
    __syncthreads();

    float* ob = out + (size_t)b * (NN * OUTROW);
    for (int idx = t; idx < NN * OUTROW; idx += 256) {
        float v = 0.f;
        if (idx < NOUT) {
            v = hb2[idx];
            #pragma unroll
            for (int m2 = 0; m2 < HDIM; ++m2)
                v += hbuf[m2] * hW2[m2 * NOUT + idx];
        }
        ob[idx] = v;
    }
}

extern "C" void kernel_launch(void* const* d_in, const int* in_sizes, int n_in,
                              void* d_out, int out_size) {
    (void)in_sizes; (void)n_in; (void)out_size;
    const float* x    = (const float*)d_in[0];
    const float* ctx  = (const float*)d_in[1];
    const float* eW1  = (const float*)d_in[2];
    const float* eb1  = (const float*)d_in[3];
    const float* eW2  = (const float*)d_in[4];
    const float* eb2  = (const float*)d_in[5];
    const float* gW   = (const float*)d_in[6];
    const float* gb   = (const float*)d_in[7];
    const float* lng  = (const float*)d_in[8];
    const float* lnb  = (const float*)d_in[9];
    const float* nW1  = (const float*)d_in[10];
    const float* nb1  = (const float*)d_in[11];
    const float* nW2  = (const float*)d_in[12];
    const float* nb2  = (const float*)d_in[13];
    const float* hW1  = (const float*)d_in[14];
    const float* hb1  = (const float*)d_in[15];
    const float* hW2  = (const float*)d_in[16];
    const float* hb2  = (const float*)d_in[17];
    float* out = (float*)d_out;

    cudaFuncSetAttribute(gnn_kernel, cudaFuncAttributeMaxDynamicSharedMemorySize,
                         SMEM_FLOATS * sizeof(float));
    gnn_kernel<<<NB, 256, SMEM_FLOATS * sizeof(float)>>>(
        x, ctx, eW1, eb1, eW2, eb2, gW, gb, lng, lnb,
        nW1, nb1, nW2, nb2, hW1, hb1, hW2, hb2, out);
}